// round 1
// baseline (speedup 1.0000x reference)
#include <cuda_runtime.h>
#include <math.h>

#define BATCH 256
#define SEQ   512
#define DIM   1024
#define VOCAB 32003

// ---------------- scratch (static device globals; no allocation) ----------------
__device__ float g_gi[BATCH * 3 * DIM];   // GRU gate pre-activations (reused)
__device__ float g_h0[BATCH * DIM];       // GRU0 hidden
__device__ float g_cat[BATCH * 2 * DIM];  // [h1 | attention summary]
__device__ float g_pre[BATCH * DIM];      // preout activations

// ---------------- packed fp32x2 helpers (FFMA2 on sm_103a) ----------------
__device__ __forceinline__ unsigned long long dup2(float x) {
    unsigned long long r;
    asm("mov.b64 %0, {%1, %1};" : "=l"(r) : "r"(__float_as_uint(x)));
    return r;
}
__device__ __forceinline__ void fma2(unsigned long long& d, unsigned long long a, unsigned long long b) {
    asm("fma.rn.f32x2 %0, %1, %2, %0;" : "+l"(d) : "l"(a), "l"(b));
}
union F2U { unsigned long long u; float2 f; };

__device__ __forceinline__ float celu1(float x) { return x > 0.f ? x : expm1f(x); }

// =====================================================================
// GEMM: C[M,N] = A[M,K] @ B[N,K]^T + bias[n]  (optional celu, optional A-row gather)
// 128x128 tile, 256 threads, 8x8 per thread, FFMA2 over n-pairs.
// M must be a multiple of 128. N guarded.
// =====================================================================
template<int ACT>
__global__ void __launch_bounds__(256)
gemm128(int N, int K,
        const float* __restrict__ A, int lda,
        const float* __restrict__ Bw, int ldb,
        float* __restrict__ C, int ldc,
        const float* __restrict__ bias,
        const int* __restrict__ gather)
{
    __shared__ float As[16][128];
    __shared__ float Bs[16][128];
    const int bm = blockIdx.y * 128;
    const int bn = blockIdx.x * 128;
    const int tid = threadIdx.x;
    const int tx = tid & 15, ty = tid >> 4;

    unsigned long long acc[8][4];
#pragma unroll
    for (int i = 0; i < 8; i++)
#pragma unroll
        for (int j = 0; j < 4; j++) acc[i][j] = 0ULL;

    for (int k0 = 0; k0 < K; k0 += 16) {
#pragma unroll
        for (int i = 0; i < 2; i++) {
            int idx = tid + i * 256;
            int r  = idx >> 2;
            int c4 = (idx & 3) << 2;
            int row  = bm + r;
            int arow = gather ? gather[row] : row;
            float4 v = *(const float4*)(A + (size_t)arow * lda + k0 + c4);
            As[c4+0][r] = v.x; As[c4+1][r] = v.y; As[c4+2][r] = v.z; As[c4+3][r] = v.w;
        }
#pragma unroll
        for (int i = 0; i < 2; i++) {
            int idx = tid + i * 256;
            int r  = idx >> 2;
            int c4 = (idx & 3) << 2;
            int row = bn + r;
            float4 v = make_float4(0.f, 0.f, 0.f, 0.f);
            if (row < N) v = *(const float4*)(Bw + (size_t)row * ldb + k0 + c4);
            Bs[c4+0][r] = v.x; Bs[c4+1][r] = v.y; Bs[c4+2][r] = v.z; Bs[c4+3][r] = v.w;
        }
        __syncthreads();
#pragma unroll
        for (int k = 0; k < 16; k++) {
            float4 a0 = *(const float4*)&As[k][ty * 4];
            float4 a1 = *(const float4*)&As[k][64 + ty * 4];
            ulonglong2 b0 = *(const ulonglong2*)&Bs[k][tx * 4];
            ulonglong2 b1 = *(const ulonglong2*)&Bs[k][64 + tx * 4];
            unsigned long long av[8] = {dup2(a0.x), dup2(a0.y), dup2(a0.z), dup2(a0.w),
                                        dup2(a1.x), dup2(a1.y), dup2(a1.z), dup2(a1.w)};
            unsigned long long bv[4] = {b0.x, b0.y, b1.x, b1.y};
#pragma unroll
            for (int i = 0; i < 8; i++)
#pragma unroll
                for (int j = 0; j < 4; j++) fma2(acc[i][j], av[i], bv[j]);
        }
        __syncthreads();
    }

#pragma unroll
    for (int i = 0; i < 8; i++) {
        int m = bm + (i < 4 ? ty * 4 + i : 64 + ty * 4 + (i - 4));
        float* crow = C + (size_t)m * ldc;
#pragma unroll
        for (int j = 0; j < 4; j++) {
            int n = bn + (j < 2 ? tx * 4 + j * 2 : 64 + tx * 4 + (j - 2) * 2);
            F2U v; v.u = acc[i][j];
            if (n < N) {
                float x = v.f.x + bias[n];
                crow[n] = ACT ? celu1(x) : x;
            }
            if (n + 1 < N) {
                float x = v.f.y + bias[n + 1];
                crow[n + 1] = ACT ? celu1(x) : x;
            }
        }
    }
}

// =====================================================================
// GEMM: 64x64 tile variant (better grid occupancy for skinny N).
// M multiple of 64; N multiple of 4 (guarded per row anyway).
// =====================================================================
template<int ACT>
__global__ void __launch_bounds__(256)
gemm64(int N, int K,
       const float* __restrict__ A, int lda,
       const float* __restrict__ Bw, int ldb,
       float* __restrict__ C, int ldc,
       const float* __restrict__ bias,
       const int* __restrict__ gather)
{
    __shared__ float As[16][64];
    __shared__ float Bs[16][64];
    const int bm = blockIdx.y * 64;
    const int bn = blockIdx.x * 64;
    const int tid = threadIdx.x;
    const int tx = tid & 15, ty = tid >> 4;

    unsigned long long acc[4][2];
#pragma unroll
    for (int i = 0; i < 4; i++) { acc[i][0] = 0ULL; acc[i][1] = 0ULL; }

    for (int k0 = 0; k0 < K; k0 += 16) {
        {
            int r  = tid >> 2;
            int c4 = (tid & 3) << 2;
            int row  = bm + r;
            int arow = gather ? gather[row] : row;
            float4 v = *(const float4*)(A + (size_t)arow * lda + k0 + c4);
            As[c4+0][r] = v.x; As[c4+1][r] = v.y; As[c4+2][r] = v.z; As[c4+3][r] = v.w;
            int rowb = bn + r;
            float4 w = make_float4(0.f, 0.f, 0.f, 0.f);
            if (rowb < N) w = *(const float4*)(Bw + (size_t)rowb * ldb + k0 + c4);
            Bs[c4+0][r] = w.x; Bs[c4+1][r] = w.y; Bs[c4+2][r] = w.z; Bs[c4+3][r] = w.w;
        }
        __syncthreads();
#pragma unroll
        for (int k = 0; k < 16; k++) {
            float4 a = *(const float4*)&As[k][ty * 4];
            ulonglong2 b = *(const ulonglong2*)&Bs[k][tx * 4];
            unsigned long long av[4] = {dup2(a.x), dup2(a.y), dup2(a.z), dup2(a.w)};
#pragma unroll
            for (int i = 0; i < 4; i++) {
                fma2(acc[i][0], av[i], b.x);
                fma2(acc[i][1], av[i], b.y);
            }
        }
        __syncthreads();
    }

#pragma unroll
    for (int i = 0; i < 4; i++) {
        int m = bm + ty * 4 + i;
        float* crow = C + (size_t)m * ldc;
#pragma unroll
        for (int j = 0; j < 2; j++) {
            int n = bn + tx * 4 + j * 2;
            F2U v; v.u = acc[i][j];
            if (n < N) {
                float x = v.f.x + bias[n];
                crow[n] = ACT ? celu1(x) : x;
            }
            if (n + 1 < N) {
                float x = v.f.y + bias[n + 1];
                crow[n + 1] = ACT ? celu1(x) : x;
            }
        }
    }
}

// =====================================================================
// GRU gate nonlinearity with zero previous hidden state:
//   gh = bhh (h_prev = 0), h' = (1 - z) * n
// gi already contains x@Wih^T + bih (from the GEMM bias).
// =====================================================================
__global__ void gru_gates(const float* __restrict__ gi, const float* __restrict__ bhh,
                          float* __restrict__ h, int ldh)
{
    int idx = blockIdx.x * blockDim.x + threadIdx.x;
    int b = idx >> 10, d = idx & 1023;
    const float* g = gi + (size_t)b * (3 * DIM);
    float r = 1.f / (1.f + expf(-(g[d]           + bhh[d])));
    float z = 1.f / (1.f + expf(-(g[DIM + d]     + bhh[DIM + d])));
    float n = tanhf(g[2 * DIM + d] + r * bhh[2 * DIM + d]);
    h[(size_t)b * ldh + d] = (1.f - z) * n;
}

// =====================================================================
// Fused single-query attention with online softmax. One block per batch row.
// Reads h1 from cat[b][0:D], writes summary to cat[b][D:2D]. Single pass over enc.
// =====================================================================
__global__ void __launch_bounds__(256)
attn_kernel(const float* __restrict__ enc, const int* __restrict__ mask,
            float* __restrict__ cat)
{
    __shared__ float h1s[DIM];
    __shared__ float tile[8][DIM];
    __shared__ float wsh[8];

    const int b   = blockIdx.x;
    const int tid = threadIdx.x;
    const float* h1 = cat + (size_t)b * (2 * DIM);

    ((float4*)h1s)[tid] = ((const float4*)h1)[tid];   // 1024 floats = 256 float4

    float m = -1e30f, l = 0.f;
    float4 acc = make_float4(0.f, 0.f, 0.f, 0.f);
    const float* encb  = enc  + (size_t)b * SEQ * DIM;
    const int*   maskb = mask + b * SEQ;
    __syncthreads();

    for (int s0 = 0; s0 < SEQ; s0 += 8) {
        const float4* src = (const float4*)(encb + (size_t)s0 * DIM);
        float4* dst = (float4*)tile;
#pragma unroll
        for (int i = 0; i < 8; i++) dst[tid + i * 256] = src[tid + i * 256];
        __syncthreads();

        // per-warp dot product: warp w handles row s0+w
        {
            int w = tid >> 5, lane = tid & 31;
            float p = 0.f;
            const float4* er = (const float4*)tile[w];
            const float4* hr = (const float4*)h1s;
#pragma unroll
            for (int i = 0; i < 8; i++) {
                float4 e  = er[lane + i * 32];
                float4 hv = hr[lane + i * 32];
                p += e.x * hv.x + e.y * hv.y + e.z * hv.z + e.w * hv.w;
            }
#pragma unroll
            for (int off = 16; off; off >>= 1) p += __shfl_xor_sync(0xffffffffu, p, off);
            if (lane == 0) wsh[w] = maskb[s0 + w] ? p : -1e30f;
        }
        __syncthreads();

        float wv[8];
        float tm = -1e30f;
#pragma unroll
        for (int j = 0; j < 8; j++) { wv[j] = wsh[j]; tm = fmaxf(tm, wv[j]); }
        float mnew  = fmaxf(m, tm);
        float scale = __expf(m - mnew);
        l *= scale;
        acc.x *= scale; acc.y *= scale; acc.z *= scale; acc.w *= scale;
#pragma unroll
        for (int j = 0; j < 8; j++) {
            float pj = __expf(wv[j] - mnew);
            l += pj;
            float4 e = *(const float4*)&tile[j][tid * 4];
            acc.x += pj * e.x; acc.y += pj * e.y; acc.z += pj * e.z; acc.w += pj * e.w;
        }
        m = mnew;
        __syncthreads();
    }

    float inv = 1.f / l;
    float4 o = make_float4(acc.x * inv, acc.y * inv, acc.z * inv, acc.w * inv);
    *(float4*)(cat + (size_t)b * (2 * DIM) + DIM + tid * 4) = o;
}

// =====================================================================
// launcher
// =====================================================================
extern "C" void kernel_launch(void* const* d_in, const int* in_sizes, int n_in,
                              void* d_out, int out_size)
{
    (void)in_sizes; (void)n_in; (void)out_size;
    const int*   tokens   = (const int*)  d_in[0];
    const float* enc      = (const float*)d_in[1];
    const int*   encmask  = (const int*)  d_in[2];
    const float* dec_emb  = (const float*)d_in[3];
    const float* Wih0     = (const float*)d_in[4];
    // d_in[5] = Whh0: unused (h0_prev == 0 -> gh0 = bhh0)
    const float* bih0     = (const float*)d_in[6];
    const float* bhh0     = (const float*)d_in[7];
    const float* Wih1     = (const float*)d_in[8];
    // d_in[9] = Whh1: unused (h1_prev == 0 -> gh1 = bhh1)
    const float* bih1     = (const float*)d_in[10];
    const float* bhh1     = (const float*)d_in[11];
    const float* preout_w = (const float*)d_in[12];
    const float* preout_b = (const float*)d_in[13];
    const float* out_w    = (const float*)d_in[14];
    const float* out_b    = (const float*)d_in[15];
    float* logits = (float*)d_out;

    float *gi, *h0, *cat, *pre;
    cudaGetSymbolAddress((void**)&gi,  g_gi);
    cudaGetSymbolAddress((void**)&h0,  g_h0);
    cudaGetSymbolAddress((void**)&cat, g_cat);
    cudaGetSymbolAddress((void**)&pre, g_pre);

    // 1) gi0 = dec_emb[tokens] @ Wih0[:, :D]^T + bih0   [256 x 3072 x 1024]
    gemm64<0><<<dim3(3 * DIM / 64, BATCH / 64), 256>>>(
        3 * DIM, DIM, dec_emb, DIM, Wih0, 2 * DIM, gi, 3 * DIM, bih0, tokens);

    // 2) h0 = gru_gates(gi0, bhh0)
    gru_gates<<<(BATCH * DIM) / 256, 256>>>(gi, bhh0, h0, DIM);

    // 3) gi1 = h0 @ Wih1^T + bih1   [256 x 3072 x 1024]
    gemm64<0><<<dim3(3 * DIM / 64, BATCH / 64), 256>>>(
        3 * DIM, DIM, h0, DIM, Wih1, DIM, gi, 3 * DIM, bih1, nullptr);

    // 4) h1 -> cat[:, 0:D]
    gru_gates<<<(BATCH * DIM) / 256, 256>>>(gi, bhh1, cat, 2 * DIM);

    // 5) attention summary -> cat[:, D:2D]  (single pass over enc, online softmax)
    attn_kernel<<<BATCH, 256>>>(enc, encmask, cat);

    // 6) pre = celu(cat @ preout_w^T + preout_b)   [256 x 1024 x 2048]
    gemm64<1><<<dim3(DIM / 64, BATCH / 64), 256>>>(
        DIM, 2 * DIM, cat, 2 * DIM, preout_w, 2 * DIM, pre, DIM, preout_b, nullptr);

    // 7) logits = pre @ out_w^T + out_b   [256 x 32003 x 1024]
    gemm128<0><<<dim3((VOCAB + 127) / 128, BATCH / 128), 256>>>(
        VOCAB, DIM, pre, DIM, out_w, DIM, logits, VOCAB, out_b, nullptr);
}

// round 4
// speedup vs baseline: 1.0179x; 1.0179x over previous
#include <cuda_runtime.h>
#include <cuda_bf16.h>
#include <cstdint>
#include <math.h>

#define BATCH 256
#define SEQ   512
#define DIM   1024
#define VOCAB 32003

// ---------------- scratch (static device globals; no allocation) ----------------
__device__ float g_gi[BATCH * 3 * DIM];
__device__ float g_h0[BATCH * DIM];
__device__ float g_cat[BATCH * 2 * DIM];
__device__ float g_pre[BATCH * DIM];

// ---------------- packed fp32x2 helpers (FFMA2) ----------------
__device__ __forceinline__ unsigned long long dup2(float x) {
    unsigned long long r;
    asm("mov.b64 %0, {%1, %1};" : "=l"(r) : "r"(__float_as_uint(x)));
    return r;
}
__device__ __forceinline__ void fma2(unsigned long long& d, unsigned long long a, unsigned long long b) {
    asm("fma.rn.f32x2 %0, %1, %2, %0;" : "+l"(d) : "l"(a), "l"(b));
}
union F2U { unsigned long long u; float2 f; };

__device__ __forceinline__ float celu1(float x) { return x > 0.f ? x : expm1f(x); }

// ---------------- bf16 split helpers ----------------
__device__ __forceinline__ void cvt2(float x, float y, uint32_t& hi, uint32_t& lo) {
    __nv_bfloat162 h = __floats2bfloat162_rn(x, y);
    __nv_bfloat162 l = __floats2bfloat162_rn(x - __low2float(h), y - __high2float(h));
    hi = *(uint32_t*)&h;
    lo = *(uint32_t*)&l;
}

__device__ __forceinline__ void mma16816(float* c, const uint32_t* a, const uint32_t* b) {
    asm volatile("mma.sync.aligned.m16n8k16.row.col.f32.bf16.bf16.f32 "
                 "{%0,%1,%2,%3}, {%4,%5,%6,%7}, {%8,%9}, {%0,%1,%2,%3};"
                 : "+f"(c[0]), "+f"(c[1]), "+f"(c[2]), "+f"(c[3])
                 : "r"(a[0]), "r"(a[1]), "r"(a[2]), "r"(a[3]), "r"(b[0]), "r"(b[1]));
}

// =====================================================================
// Logits GEMM via mma.sync bf16, split-fp32 (3 terms).
// C[256, 32003] = A[256,1024] @ B[32003,1024]^T + bias
// CTA tile 128x128, 8 warps (2x4), warp tile 64x32, K-chunk 32.
// Smem planes (per buffer): A_hi, A_lo, B_hi, B_lo; 128 rows x 24 words,
// permuted k-pairs so each fragment = one LDS.64, pitch 24 -> conflict-free.
// =====================================================================
#define LG_PITCH 24
#define LG_PLANE (128 * LG_PITCH)   // 3072 words
#define LG_BUF   (4 * LG_PLANE)     // 12288 words
#define LG_SMEM_BYTES (2 * LG_BUF * 4)  // 98304

__global__ void __launch_bounds__(256, 1)
logits_mma(const float* __restrict__ A, const float* __restrict__ Bw,
           const float* __restrict__ bias, float* __restrict__ C)
{
    extern __shared__ uint32_t sm[];
    const int t    = threadIdx.x;
    const int lane = t & 31;
    const int wid  = t >> 5;
    const int wm   = wid >> 2;       // 0..1
    const int wn   = wid & 3;        // 0..3
    const int bm   = blockIdx.x & 1;
    const int bn   = blockIdx.x >> 1;

    // ---- producer role: one thread per smem row ----
    const bool isA = t < 128;
    const int  row = isA ? t : t - 128;
    const float* gsrc;
    if (isA) {
        gsrc = A + (size_t)(bm * 128 + row) * DIM;
    } else {
        int ng = bn * 128 + row;
        if (ng > VOCAB - 1) ng = VOCAB - 1;
        gsrc = Bw + (size_t)ng * DIM;
    }
    const int rot = ((t & 31) >> 2) * 3;

    float4 pf[8];
    auto ldchunk = [&](int ch) {
        const float4* p = (const float4*)(gsrc + ch * 32);
#pragma unroll
        for (int i = 0; i < 8; i++) pf[i] = p[i];
    };
    auto stchunk = [&](int buf) {
        uint32_t hiw[16], low[16];
        const float* f = (const float*)pf;
#pragma unroll
        for (int h = 0; h < 2; h++)
#pragma unroll
            for (int p = 0; p < 8; p++) {
                int w = h * 8 + (p & 3) * 2 + (p >> 2);
                cvt2(f[16 * h + 2 * p], f[16 * h + 2 * p + 1], hiw[w], low[w]);
            }
        uint32_t* basehi = sm + buf * LG_BUF + (isA ? 0 : 2 * LG_PLANE) + row * LG_PITCH;
        uint32_t* baselo = basehi + LG_PLANE;
#pragma unroll
        for (int j = 0; j < 16; j++) {
            int w = (j + rot) & 15;
            basehi[w] = hiw[w];
        }
#pragma unroll
        for (int j = 0; j < 16; j++) {
            int w = (j + rot) & 15;
            baselo[w] = low[w];
        }
    };

    float acc[4][4][4];
#pragma unroll
    for (int i = 0; i < 4; i++)
#pragma unroll
        for (int j = 0; j < 4; j++)
#pragma unroll
            for (int k = 0; k < 4; k++) acc[i][j][k] = 0.f;

    ldchunk(0);
    stchunk(0);
    __syncthreads();

    const int NCHUNK = DIM / 32;   // 32
    for (int ch = 0; ch < NCHUNK; ch++) {
        if (ch + 1 < NCHUNK) ldchunk(ch + 1);

        const uint32_t* base = sm + (ch & 1) * LG_BUF;
        const uint32_t* Ah = base;
        const uint32_t* Al = base + LG_PLANE;
        const uint32_t* Bh = base + 2 * LG_PLANE;
        const uint32_t* Bl = base + 3 * LG_PLANE;
        const int ko_lane = (lane & 3) * 2;
        const int rA = wm * 64 + (lane >> 2);
        const int cB = wn * 32 + (lane >> 2);

#pragma unroll
        for (int step = 0; step < 2; step++) {
            const int ko = step * 8 + ko_lane;
            uint32_t ah[4][4], al[4][4];
#pragma unroll
            for (int mt = 0; mt < 4; mt++) {
                int r = rA + mt * 16;
                uint2 x0 = *(const uint2*)(Ah + r * LG_PITCH + ko);
                uint2 x1 = *(const uint2*)(Ah + (r + 8) * LG_PITCH + ko);
                ah[mt][0] = x0.x; ah[mt][1] = x1.x; ah[mt][2] = x0.y; ah[mt][3] = x1.y;
                uint2 y0 = *(const uint2*)(Al + r * LG_PITCH + ko);
                uint2 y1 = *(const uint2*)(Al + (r + 8) * LG_PITCH + ko);
                al[mt][0] = y0.x; al[mt][1] = y1.x; al[mt][2] = y0.y; al[mt][3] = y1.y;
            }
            uint32_t bh[4][2], bl[4][2];
#pragma unroll
            for (int nt = 0; nt < 4; nt++) {
                int c = cB + nt * 8;
                uint2 v = *(const uint2*)(Bh + c * LG_PITCH + ko);
                bh[nt][0] = v.x; bh[nt][1] = v.y;
                uint2 u = *(const uint2*)(Bl + c * LG_PITCH + ko);
                bl[nt][0] = u.x; bl[nt][1] = u.y;
            }
#pragma unroll
            for (int mt = 0; mt < 4; mt++)
#pragma unroll
                for (int nt = 0; nt < 4; nt++) {
                    mma16816(acc[mt][nt], ah[mt], bh[nt]);
                    mma16816(acc[mt][nt], al[mt], bh[nt]);
                    mma16816(acc[mt][nt], ah[mt], bl[nt]);
                }
        }
        __syncthreads();
        if (ch + 1 < NCHUNK) {
            stchunk((ch + 1) & 1);
            __syncthreads();
        }
    }

    // ---- epilogue: direct gmem stores with bias ----
    const int m_base = bm * 128 + wm * 64 + (lane >> 2);
    const int n_base = bn * 128 + wn * 32 + (lane & 3) * 2;
#pragma unroll
    for (int mt = 0; mt < 4; mt++) {
        int m0 = m_base + mt * 16;
        float* cr0 = C + (size_t)m0 * VOCAB;
        float* cr1 = C + (size_t)(m0 + 8) * VOCAB;
#pragma unroll
        for (int nt = 0; nt < 4; nt++) {
            int n = n_base + nt * 8;
            if (n < VOCAB) {
                cr0[n] = acc[mt][nt][0] + bias[n];
                cr1[n] = acc[mt][nt][2] + bias[n];
            }
            if (n + 1 < VOCAB) {
                cr0[n + 1] = acc[mt][nt][1] + bias[n + 1];
                cr1[n + 1] = acc[mt][nt][3] + bias[n + 1];
            }
        }
    }
}

// =====================================================================
// 64x64 FFMA2 GEMM for the small GEMMs (gi0, gi1, preout)
// =====================================================================
template<int ACT>
__global__ void __launch_bounds__(256)
gemm64(int N, int K,
       const float* __restrict__ A, int lda,
       const float* __restrict__ Bw, int ldb,
       float* __restrict__ C, int ldc,
       const float* __restrict__ bias,
       const int* __restrict__ gather)
{
    __shared__ float As[16][64];
    __shared__ float Bs[16][64];
    const int bm = blockIdx.y * 64;
    const int bn = blockIdx.x * 64;
    const int tid = threadIdx.x;
    const int tx = tid & 15, ty = tid >> 4;

    unsigned long long acc[4][2];
#pragma unroll
    for (int i = 0; i < 4; i++) { acc[i][0] = 0ULL; acc[i][1] = 0ULL; }

    for (int k0 = 0; k0 < K; k0 += 16) {
        {
            int r  = tid >> 2;
            int c4 = (tid & 3) << 2;
            int row  = bm + r;
            int arow = gather ? gather[row] : row;
            float4 v = *(const float4*)(A + (size_t)arow * lda + k0 + c4);
            As[c4+0][r] = v.x; As[c4+1][r] = v.y; As[c4+2][r] = v.z; As[c4+3][r] = v.w;
            int rowb = bn + r;
            float4 w = make_float4(0.f, 0.f, 0.f, 0.f);
            if (rowb < N) w = *(const float4*)(Bw + (size_t)rowb * ldb + k0 + c4);
            Bs[c4+0][r] = w.x; Bs[c4+1][r] = w.y; Bs[c4+2][r] = w.z; Bs[c4+3][r] = w.w;
        }
        __syncthreads();
#pragma unroll
        for (int k = 0; k < 16; k++) {
            float4 a = *(const float4*)&As[k][ty * 4];
            ulonglong2 b = *(const ulonglong2*)&Bs[k][tx * 4];
            unsigned long long av[4] = {dup2(a.x), dup2(a.y), dup2(a.z), dup2(a.w)};
#pragma unroll
            for (int i = 0; i < 4; i++) {
                fma2(acc[i][0], av[i], b.x);
                fma2(acc[i][1], av[i], b.y);
            }
        }
        __syncthreads();
    }

#pragma unroll
    for (int i = 0; i < 4; i++) {
        int m = bm + ty * 4 + i;
        float* crow = C + (size_t)m * ldc;
#pragma unroll
        for (int j = 0; j < 2; j++) {
            int n = bn + tx * 4 + j * 2;
            F2U v; v.u = acc[i][j];
            if (n < N) {
                float x = v.f.x + bias[n];
                crow[n] = ACT ? celu1(x) : x;
            }
            if (n + 1 < N) {
                float x = v.f.y + bias[n + 1];
                crow[n + 1] = ACT ? celu1(x) : x;
            }
        }
    }
}

// =====================================================================
// GRU gates (zero previous hidden state): h' = (1-z) * n
// =====================================================================
__global__ void gru_gates(const float* __restrict__ gi, const float* __restrict__ bhh,
                          float* __restrict__ h, int ldh)
{
    int idx = blockIdx.x * blockDim.x + threadIdx.x;
    int b = idx >> 10, d = idx & 1023;
    const float* g = gi + (size_t)b * (3 * DIM);
    float r = 1.f / (1.f + expf(-(g[d]           + bhh[d])));
    float z = 1.f / (1.f + expf(-(g[DIM + d]     + bhh[DIM + d])));
    float n = tanhf(g[2 * DIM + d] + r * bhh[2 * DIM + d]);
    h[(size_t)b * ldh + d] = (1.f - z) * n;
}

// =====================================================================
// Fused single-query attention, online softmax, one block per batch row
// =====================================================================
__global__ void __launch_bounds__(256)
attn_kernel(const float* __restrict__ enc, const int* __restrict__ mask,
            float* __restrict__ cat)
{
    __shared__ float h1s[DIM];
    __shared__ float tile[8][DIM];
    __shared__ float wsh[8];

    const int b   = blockIdx.x;
    const int tid = threadIdx.x;
    const float* h1 = cat + (size_t)b * (2 * DIM);

    ((float4*)h1s)[tid] = ((const float4*)h1)[tid];

    float m = -1e30f, l = 0.f;
    float4 acc = make_float4(0.f, 0.f, 0.f, 0.f);
    const float* encb  = enc  + (size_t)b * SEQ * DIM;
    const int*   maskb = mask + b * SEQ;
    __syncthreads();

    for (int s0 = 0; s0 < SEQ; s0 += 8) {
        const float4* src = (const float4*)(encb + (size_t)s0 * DIM);
        float4* dst = (float4*)tile;
#pragma unroll
        for (int i = 0; i < 8; i++) dst[tid + i * 256] = src[tid + i * 256];
        __syncthreads();

        {
            int w = tid >> 5, lane = tid & 31;
            float p = 0.f;
            const float4* er = (const float4*)tile[w];
            const float4* hr = (const float4*)h1s;
#pragma unroll
            for (int i = 0; i < 8; i++) {
                float4 e  = er[lane + i * 32];
                float4 hv = hr[lane + i * 32];
                p += e.x * hv.x + e.y * hv.y + e.z * hv.z + e.w * hv.w;
            }
#pragma unroll
            for (int off = 16; off; off >>= 1) p += __shfl_xor_sync(0xffffffffu, p, off);
            if (lane == 0) wsh[w] = maskb[s0 + w] ? p : -1e30f;
        }
        __syncthreads();

        float wv[8];
        float tm = -1e30f;
#pragma unroll
        for (int j = 0; j < 8; j++) { wv[j] = wsh[j]; tm = fmaxf(tm, wv[j]); }
        float mnew  = fmaxf(m, tm);
        float scale = __expf(m - mnew);
        l *= scale;
        acc.x *= scale; acc.y *= scale; acc.z *= scale; acc.w *= scale;
#pragma unroll
        for (int j = 0; j < 8; j++) {
            float pj = __expf(wv[j] - mnew);
            l += pj;
            float4 e = *(const float4*)&tile[j][tid * 4];
            acc.x += pj * e.x; acc.y += pj * e.y; acc.z += pj * e.z; acc.w += pj * e.w;
        }
        m = mnew;
        __syncthreads();
    }

    float inv = 1.f / l;
    float4 o = make_float4(acc.x * inv, acc.y * inv, acc.z * inv, acc.w * inv);
    *(float4*)(cat + (size_t)b * (2 * DIM) + DIM + tid * 4) = o;
}

// =====================================================================
// launcher
// =====================================================================
extern "C" void kernel_launch(void* const* d_in, const int* in_sizes, int n_in,
                              void* d_out, int out_size)
{
    (void)in_sizes; (void)n_in; (void)out_size;
    const int*   tokens   = (const int*)  d_in[0];
    const float* enc      = (const float*)d_in[1];
    const int*   encmask  = (const int*)  d_in[2];
    const float* dec_emb  = (const float*)d_in[3];
    const float* Wih0     = (const float*)d_in[4];
    const float* bih0     = (const float*)d_in[6];
    const float* bhh0     = (const float*)d_in[7];
    const float* Wih1     = (const float*)d_in[8];
    const float* bih1     = (const float*)d_in[10];
    const float* bhh1     = (const float*)d_in[11];
    const float* preout_w = (const float*)d_in[12];
    const float* preout_b = (const float*)d_in[13];
    const float* out_w    = (const float*)d_in[14];
    const float* out_b    = (const float*)d_in[15];
    float* logits = (float*)d_out;

    float *gi, *h0, *cat, *pre;
    cudaGetSymbolAddress((void**)&gi,  g_gi);
    cudaGetSymbolAddress((void**)&h0,  g_h0);
    cudaGetSymbolAddress((void**)&cat, g_cat);
    cudaGetSymbolAddress((void**)&pre, g_pre);

    static int smem_set = 0;
    if (!smem_set) {
        cudaFuncSetAttribute(logits_mma, cudaFuncAttributeMaxDynamicSharedMemorySize, LG_SMEM_BYTES);
        smem_set = 1;
    }

    // 1) gi0 = dec_emb[tokens] @ Wih0[:, :D]^T + bih0
    gemm64<0><<<dim3(3 * DIM / 64, BATCH / 64), 256>>>(
        3 * DIM, DIM, dec_emb, DIM, Wih0, 2 * DIM, gi, 3 * DIM, bih0, tokens);

    // 2) h0
    gru_gates<<<(BATCH * DIM) / 256, 256>>>(gi, bhh0, h0, DIM);

    // 3) gi1 = h0 @ Wih1^T + bih1
    gemm64<0><<<dim3(3 * DIM / 64, BATCH / 64), 256>>>(
        3 * DIM, DIM, h0, DIM, Wih1, DIM, gi, 3 * DIM, bih1, nullptr);

    // 4) h1 -> cat[:, 0:D]
    gru_gates<<<(BATCH * DIM) / 256, 256>>>(gi, bhh1, cat, 2 * DIM);

    // 5) attention summary -> cat[:, D:2D]
    attn_kernel<<<BATCH, 256>>>(enc, encmask, cat);

    // 6) pre = celu(cat @ preout_w^T + preout_b)
    gemm64<1><<<dim3(DIM / 64, BATCH / 64), 256>>>(
        DIM, 2 * DIM, cat, 2 * DIM, preout_w, 2 * DIM, pre, DIM, preout_b, nullptr);

    // 7) logits = pre @ out_w^T + out_b   (mma.sync bf16 split-fp32)
    logits_mma<<<((VOCAB + 127) / 128) * 2, 256, LG_SMEM_BYTES>>>(pre, out_w, out_b, logits);
}

// round 5
// speedup vs baseline: 1.0928x; 1.0736x over previous
#include <cuda_runtime.h>
#include <cuda_bf16.h>
#include <cstdint>
#include <math.h>

#define BATCH 256
#define SEQ   512
#define DIM   1024
#define VOCAB 32003

// ---------------- scratch (static device globals; no allocation) ----------------
__device__ float g_gi[BATCH * 3 * DIM];
__device__ float g_h0[BATCH * DIM];
__device__ float g_cat[BATCH * 2 * DIM];
__device__ float g_pre[BATCH * DIM];

// ---------------- packed fp32x2 helpers (FFMA2) ----------------
__device__ __forceinline__ unsigned long long dup2(float x) {
    unsigned long long r;
    asm("mov.b64 %0, {%1, %1};" : "=l"(r) : "r"(__float_as_uint(x)));
    return r;
}
__device__ __forceinline__ void fma2(unsigned long long& d, unsigned long long a, unsigned long long b) {
    asm("fma.rn.f32x2 %0, %1, %2, %0;" : "+l"(d) : "l"(a), "l"(b));
}
union F2U { unsigned long long u; float2 f; };

__device__ __forceinline__ float celu1(float x) { return x > 0.f ? x : expm1f(x); }

// ---------------- bf16 split helpers ----------------
__device__ __forceinline__ void cvt2(float x, float y, uint32_t& hi, uint32_t& lo) {
    __nv_bfloat162 h = __floats2bfloat162_rn(x, y);
    __nv_bfloat162 l = __floats2bfloat162_rn(x - __low2float(h), y - __high2float(h));
    hi = *(uint32_t*)&h;
    lo = *(uint32_t*)&l;
}

__device__ __forceinline__ void mma16816(float* c, const uint32_t* a, const uint32_t* b) {
    asm volatile("mma.sync.aligned.m16n8k16.row.col.f32.bf16.bf16.f32 "
                 "{%0,%1,%2,%3}, {%4,%5,%6,%7}, {%8,%9}, {%0,%1,%2,%3};"
                 : "+f"(c[0]), "+f"(c[1]), "+f"(c[2]), "+f"(c[3])
                 : "r"(a[0]), "r"(a[1]), "r"(a[2]), "r"(a[3]), "r"(b[0]), "r"(b[1]));
}

// =====================================================================
// Logits GEMM via mma.sync bf16, split-fp32 (3 terms).
// C[256, 32003] = A[256,1024] @ B[32003,1024]^T + bias
// CTA tile 128x128, 8 warps (2x4), warp tile 64x32, K-chunk 32.
// Smem planes per buffer: A_hi, A_lo, B_hi, B_lo; 128 rows x pitch-20 words
// (16 data + 4 pad). Pitch 20 makes both STS.128 (producer) and the
// per-fragment LDS.32 (consumer) bank-conflict-free with NO permutation.
// Single __syncthreads per chunk; prefetch distance = 1 full chunk.
// =====================================================================
#define LP    20
#define PLANE (128 * LP)       // 2560 words
#define BUFW  (4 * PLANE)      // 10240 words
#define LG_SMEM_BYTES (2 * BUFW * 4)   // 81920 bytes

__global__ void __launch_bounds__(256, 1)
logits_mma(const float* __restrict__ A, const float* __restrict__ Bw,
           const float* __restrict__ bias, float* __restrict__ C)
{
    extern __shared__ uint32_t sm[];
    const int t    = threadIdx.x;
    const int lane = t & 31;
    const int wid  = t >> 5;
    const int wm   = wid >> 2;       // 0..1
    const int wn   = wid & 3;        // 0..3
    const int bm   = blockIdx.x & 1;
    const int bn   = blockIdx.x >> 1;

    // ---- producer role: one thread per smem row ----
    const bool isA = t < 128;
    const int  row = isA ? t : t - 128;
    const float* gsrc;
    if (isA) {
        gsrc = A + (size_t)(bm * 128 + row) * DIM;
    } else {
        int ng = bn * 128 + row;
        if (ng > VOCAB - 1) ng = VOCAB - 1;
        gsrc = Bw + (size_t)ng * DIM;
    }
    uint32_t* myhi = sm + (isA ? 0 : 2 * PLANE) + row * LP;

    float4 pf[8];
    auto ldchunk = [&](int ch) {
        const float4* p = (const float4*)(gsrc + ch * 32);
#pragma unroll
        for (int i = 0; i < 8; i++) pf[i] = p[i];
    };
    auto stchunk = [&](int buf) {
        uint32_t* hi = myhi + buf * BUFW;
        uint32_t* lo = hi + PLANE;
#pragma unroll
        for (int q = 0; q < 4; q++) {
            const float* f = (const float*)&pf[2 * q];
            uint4 h, l;
            cvt2(f[0], f[1], h.x, l.x);
            cvt2(f[2], f[3], h.y, l.y);
            cvt2(f[4], f[5], h.z, l.z);
            cvt2(f[6], f[7], h.w, l.w);
            *(uint4*)(hi + q * 4) = h;
            *(uint4*)(lo + q * 4) = l;
        }
    };

    float acc[4][4][4];
#pragma unroll
    for (int i = 0; i < 4; i++)
#pragma unroll
        for (int j = 0; j < 4; j++)
#pragma unroll
            for (int k = 0; k < 4; k++) acc[i][j][k] = 0.f;

    const int NCHUNK = DIM / 32;   // 32
    ldchunk(0);
    stchunk(0);
    ldchunk(1);
    __syncthreads();

    const int rA = wm * 64 + (lane >> 2);
    const int cB = wn * 32 + (lane >> 2);
    const int wl = lane & 3;

    for (int ch = 0; ch < NCHUNK; ch++) {
        // store prefetched chunk ch+1 into the other buffer (its readers
        // finished before the sync that ended iteration ch-1)
        if (ch + 1 < NCHUNK) stchunk((ch + 1) & 1);
        if (ch + 2 < NCHUNK) ldchunk(ch + 2);

        const uint32_t* base = sm + (ch & 1) * BUFW;
        const uint32_t* Ah = base;
        const uint32_t* Al = base + PLANE;
        const uint32_t* Bh = base + 2 * PLANE;
        const uint32_t* Bl = base + 3 * PLANE;

#pragma unroll
        for (int step = 0; step < 2; step++) {
            const int w = step * 8 + wl;
            uint32_t ah[4][4], al[4][4];
#pragma unroll
            for (int mt = 0; mt < 4; mt++) {
                const uint32_t* p0 = Ah + (rA + mt * 16) * LP + w;
                ah[mt][0] = p0[0];
                ah[mt][1] = p0[8 * LP];
                ah[mt][2] = p0[4];
                ah[mt][3] = p0[8 * LP + 4];
                const uint32_t* p1 = Al + (rA + mt * 16) * LP + w;
                al[mt][0] = p1[0];
                al[mt][1] = p1[8 * LP];
                al[mt][2] = p1[4];
                al[mt][3] = p1[8 * LP + 4];
            }
            uint32_t bh[4][2], bl[4][2];
#pragma unroll
            for (int nt = 0; nt < 4; nt++) {
                const uint32_t* pb = Bh + (cB + nt * 8) * LP + w;
                bh[nt][0] = pb[0];
                bh[nt][1] = pb[4];
                const uint32_t* pc = Bl + (cB + nt * 8) * LP + w;
                bl[nt][0] = pc[0];
                bl[nt][1] = pc[4];
            }
#pragma unroll
            for (int mt = 0; mt < 4; mt++)
#pragma unroll
                for (int nt = 0; nt < 4; nt++) {
                    mma16816(acc[mt][nt], ah[mt], bh[nt]);
                    mma16816(acc[mt][nt], al[mt], bh[nt]);
                    mma16816(acc[mt][nt], ah[mt], bl[nt]);
                }
        }
        __syncthreads();
    }

    // ---- epilogue: transpose through smem (reuse buffers), coalesced STG ----
    {
        float* tr = (float*)sm;     // [128][132]
        const int P = 132;
        const int m0 = wm * 64 + (lane >> 2);
        const int n0 = wn * 32 + (lane & 3) * 2;
#pragma unroll
        for (int mt = 0; mt < 4; mt++) {
#pragma unroll
            for (int nt = 0; nt < 4; nt++) {
                int m = m0 + mt * 16, n = n0 + nt * 8;
                tr[m * P + n]           = acc[mt][nt][0];
                tr[m * P + n + 1]       = acc[mt][nt][1];
                tr[(m + 8) * P + n]     = acc[mt][nt][2];
                tr[(m + 8) * P + n + 1] = acc[mt][nt][3];
            }
        }
        __syncthreads();
        const int mbase = bm * 128;
        const int nbase = bn * 128;
#pragma unroll 4
        for (int it = 0; it < 64; it++) {
            int idx = it * 256 + t;
            int m = idx >> 7, c = idx & 127;
            int n = nbase + c;
            if (n < VOCAB)
                C[(size_t)(mbase + m) * VOCAB + n] = tr[m * P + c] + bias[n];
        }
    }
}

// =====================================================================
// 64x64 FFMA2 GEMM for the small GEMMs (gi0, gi1, preout)
// =====================================================================
template<int ACT>
__global__ void __launch_bounds__(256)
gemm64(int N, int K,
       const float* __restrict__ A, int lda,
       const float* __restrict__ Bw, int ldb,
       float* __restrict__ C, int ldc,
       const float* __restrict__ bias,
       const int* __restrict__ gather)
{
    __shared__ float As[16][64];
    __shared__ float Bs[16][64];
    const int bm = blockIdx.y * 64;
    const int bn = blockIdx.x * 64;
    const int tid = threadIdx.x;
    const int tx = tid & 15, ty = tid >> 4;

    unsigned long long acc[4][2];
#pragma unroll
    for (int i = 0; i < 4; i++) { acc[i][0] = 0ULL; acc[i][1] = 0ULL; }

    for (int k0 = 0; k0 < K; k0 += 16) {
        {
            int r  = tid >> 2;
            int c4 = (tid & 3) << 2;
            int row  = bm + r;
            int arow = gather ? gather[row] : row;
            float4 v = *(const float4*)(A + (size_t)arow * lda + k0 + c4);
            As[c4+0][r] = v.x; As[c4+1][r] = v.y; As[c4+2][r] = v.z; As[c4+3][r] = v.w;
            int rowb = bn + r;
            float4 w = make_float4(0.f, 0.f, 0.f, 0.f);
            if (rowb < N) w = *(const float4*)(Bw + (size_t)rowb * ldb + k0 + c4);
            Bs[c4+0][r] = w.x; Bs[c4+1][r] = w.y; Bs[c4+2][r] = w.z; Bs[c4+3][r] = w.w;
        }
        __syncthreads();
#pragma unroll
        for (int k = 0; k < 16; k++) {
            float4 a = *(const float4*)&As[k][ty * 4];
            ulonglong2 b = *(const ulonglong2*)&Bs[k][tx * 4];
            unsigned long long av[4] = {dup2(a.x), dup2(a.y), dup2(a.z), dup2(a.w)};
#pragma unroll
            for (int i = 0; i < 4; i++) {
                fma2(acc[i][0], av[i], b.x);
                fma2(acc[i][1], av[i], b.y);
            }
        }
        __syncthreads();
    }

#pragma unroll
    for (int i = 0; i < 4; i++) {
        int m = bm + ty * 4 + i;
        float* crow = C + (size_t)m * ldc;
#pragma unroll
        for (int j = 0; j < 2; j++) {
            int n = bn + tx * 4 + j * 2;
            F2U v; v.u = acc[i][j];
            if (n < N) {
                float x = v.f.x + bias[n];
                crow[n] = ACT ? celu1(x) : x;
            }
            if (n + 1 < N) {
                float x = v.f.y + bias[n + 1];
                crow[n + 1] = ACT ? celu1(x) : x;
            }
        }
    }
}

// =====================================================================
// GRU gates (zero previous hidden state): h' = (1-z) * n
// =====================================================================
__global__ void gru_gates(const float* __restrict__ gi, const float* __restrict__ bhh,
                          float* __restrict__ h, int ldh)
{
    int idx = blockIdx.x * blockDim.x + threadIdx.x;
    int b = idx >> 10, d = idx & 1023;
    const float* g = gi + (size_t)b * (3 * DIM);
    float r = 1.f / (1.f + expf(-(g[d]           + bhh[d])));
    float z = 1.f / (1.f + expf(-(g[DIM + d]     + bhh[DIM + d])));
    float n = tanhf(g[2 * DIM + d] + r * bhh[2 * DIM + d]);
    h[(size_t)b * ldh + d] = (1.f - z) * n;
}

// =====================================================================
// Fused single-query attention, online softmax, one block per batch row
// =====================================================================
__global__ void __launch_bounds__(256)
attn_kernel(const float* __restrict__ enc, const int* __restrict__ mask,
            float* __restrict__ cat)
{
    __shared__ float h1s[DIM];
    __shared__ float tile[8][DIM];
    __shared__ float wsh[8];

    const int b   = blockIdx.x;
    const int tid = threadIdx.x;
    const float* h1 = cat + (size_t)b * (2 * DIM);

    ((float4*)h1s)[tid] = ((const float4*)h1)[tid];

    float m = -1e30f, l = 0.f;
    float4 acc = make_float4(0.f, 0.f, 0.f, 0.f);
    const float* encb  = enc  + (size_t)b * SEQ * DIM;
    const int*   maskb = mask + b * SEQ;
    __syncthreads();

    for (int s0 = 0; s0 < SEQ; s0 += 8) {
        const float4* src = (const float4*)(encb + (size_t)s0 * DIM);
        float4* dst = (float4*)tile;
#pragma unroll
        for (int i = 0; i < 8; i++) dst[tid + i * 256] = src[tid + i * 256];
        __syncthreads();

        {
            int w = tid >> 5, lane = tid & 31;
            float p = 0.f;
            const float4* er = (const float4*)tile[w];
            const float4* hr = (const float4*)h1s;
#pragma unroll
            for (int i = 0; i < 8; i++) {
                float4 e  = er[lane + i * 32];
                float4 hv = hr[lane + i * 32];
                p += e.x * hv.x + e.y * hv.y + e.z * hv.z + e.w * hv.w;
            }
#pragma unroll
            for (int off = 16; off; off >>= 1) p += __shfl_xor_sync(0xffffffffu, p, off);
            if (lane == 0) wsh[w] = maskb[s0 + w] ? p : -1e30f;
        }
        __syncthreads();

        float wv[8];
        float tm = -1e30f;
#pragma unroll
        for (int j = 0; j < 8; j++) { wv[j] = wsh[j]; tm = fmaxf(tm, wv[j]); }
        float mnew  = fmaxf(m, tm);
        float scale = __expf(m - mnew);
        l *= scale;
        acc.x *= scale; acc.y *= scale; acc.z *= scale; acc.w *= scale;
#pragma unroll
        for (int j = 0; j < 8; j++) {
            float pj = __expf(wv[j] - mnew);
            l += pj;
            float4 e = *(const float4*)&tile[j][tid * 4];
            acc.x += pj * e.x; acc.y += pj * e.y; acc.z += pj * e.z; acc.w += pj * e.w;
        }
        m = mnew;
        __syncthreads();
    }

    float inv = 1.f / l;
    float4 o = make_float4(acc.x * inv, acc.y * inv, acc.z * inv, acc.w * inv);
    *(float4*)(cat + (size_t)b * (2 * DIM) + DIM + tid * 4) = o;
}

// =====================================================================
// launcher
// =====================================================================
extern "C" void kernel_launch(void* const* d_in, const int* in_sizes, int n_in,
                              void* d_out, int out_size)
{
    (void)in_sizes; (void)n_in; (void)out_size;
    const int*   tokens   = (const int*)  d_in[0];
    const float* enc      = (const float*)d_in[1];
    const int*   encmask  = (const int*)  d_in[2];
    const float* dec_emb  = (const float*)d_in[3];
    const float* Wih0     = (const float*)d_in[4];
    const float* bih0     = (const float*)d_in[6];
    const float* bhh0     = (const float*)d_in[7];
    const float* Wih1     = (const float*)d_in[8];
    const float* bih1     = (const float*)d_in[10];
    const float* bhh1     = (const float*)d_in[11];
    const float* preout_w = (const float*)d_in[12];
    const float* preout_b = (const float*)d_in[13];
    const float* out_w    = (const float*)d_in[14];
    const float* out_b    = (const float*)d_in[15];
    float* logits = (float*)d_out;

    float *gi, *h0, *cat, *pre;
    cudaGetSymbolAddress((void**)&gi,  g_gi);
    cudaGetSymbolAddress((void**)&h0,  g_h0);
    cudaGetSymbolAddress((void**)&cat, g_cat);
    cudaGetSymbolAddress((void**)&pre, g_pre);

    static int smem_set = 0;
    if (!smem_set) {
        cudaFuncSetAttribute(logits_mma, cudaFuncAttributeMaxDynamicSharedMemorySize, LG_SMEM_BYTES);
        smem_set = 1;
    }

    // 1) gi0 = dec_emb[tokens] @ Wih0[:, :D]^T + bih0
    gemm64<0><<<dim3(3 * DIM / 64, BATCH / 64), 256>>>(
        3 * DIM, DIM, dec_emb, DIM, Wih0, 2 * DIM, gi, 3 * DIM, bih0, tokens);

    // 2) h0
    gru_gates<<<(BATCH * DIM) / 256, 256>>>(gi, bhh0, h0, DIM);

    // 3) gi1 = h0 @ Wih1^T + bih1
    gemm64<0><<<dim3(3 * DIM / 64, BATCH / 64), 256>>>(
        3 * DIM, DIM, h0, DIM, Wih1, DIM, gi, 3 * DIM, bih1, nullptr);

    // 4) h1 -> cat[:, 0:D]
    gru_gates<<<(BATCH * DIM) / 256, 256>>>(gi, bhh1, cat, 2 * DIM);

    // 5) attention summary -> cat[:, D:2D]
    attn_kernel<<<BATCH, 256>>>(enc, encmask, cat);

    // 6) pre = celu(cat @ preout_w^T + preout_b)
    gemm64<1><<<dim3(DIM / 64, BATCH / 64), 256>>>(
        DIM, 2 * DIM, cat, 2 * DIM, preout_w, 2 * DIM, pre, DIM, preout_b, nullptr);

    // 7) logits = pre @ out_w^T + out_b   (mma.sync bf16 split-fp32)
    logits_mma<<<((VOCAB + 127) / 128) * 2, 256, LG_SMEM_BYTES>>>(pre, out_w, out_b, logits);
}

// round 6
// speedup vs baseline: 1.3647x; 1.2488x over previous
#include <cuda_runtime.h>
#include <cuda_fp16.h>
#include <cstdint>
#include <math.h>

#define BATCH 256
#define SEQ   512
#define DIM   1024
#define VOCAB 32003

// ---------------- scratch (static device globals; no allocation) ----------------
__device__ float g_gi[BATCH * 3 * DIM];
__device__ float g_h0[BATCH * DIM];
__device__ float g_cat[BATCH * 2 * DIM];
__device__ float g_pre[BATCH * DIM];

// ---------------- packed fp32x2 helpers (FFMA2) ----------------
__device__ __forceinline__ unsigned long long dup2(float x) {
    unsigned long long r;
    asm("mov.b64 %0, {%1, %1};" : "=l"(r) : "r"(__float_as_uint(x)));
    return r;
}
__device__ __forceinline__ void fma2(unsigned long long& d, unsigned long long a, unsigned long long b) {
    asm("fma.rn.f32x2 %0, %1, %2, %0;" : "+l"(d) : "l"(a), "l"(b));
}
union F2U { unsigned long long u; float2 f; };

__device__ __forceinline__ float celu1(float x) { return x > 0.f ? x : expm1f(x); }

// ---------------- fp16 helpers ----------------
__device__ __forceinline__ uint32_t h2pack(float x, float y) {
    __half2 h = __floats2half2_rn(x, y);
    return *(uint32_t*)&h;
}
__device__ __forceinline__ uint4 packq(float4 x, float4 y) {
    uint4 w;
    w.x = h2pack(x.x, x.y);
    w.y = h2pack(y.x, y.y);
    w.z = h2pack(x.z, x.w);
    w.w = h2pack(y.z, y.w);
    return w;
}
__device__ __forceinline__ void mmaf16(float* c, uint32_t a0, uint32_t a1, uint32_t a2,
                                       uint32_t a3, uint32_t b0, uint32_t b1) {
    asm volatile("mma.sync.aligned.m16n8k16.row.col.f32.f16.f16.f32 "
                 "{%0,%1,%2,%3}, {%4,%5,%6,%7}, {%8,%9}, {%0,%1,%2,%3};"
                 : "+f"(c[0]), "+f"(c[1]), "+f"(c[2]), "+f"(c[3])
                 : "r"(a0), "r"(a1), "r"(a2), "r"(a3), "r"(b0), "r"(b1));
}

// ---------------- cp.async helpers ----------------
#define CP_ASYNC16(dst, src) \
    asm volatile("cp.async.cg.shared.global [%0], [%1], 16;" :: "r"(dst), "l"(src))
#define CP_COMMIT() asm volatile("cp.async.commit_group;" ::: "memory")
#define CP_WAIT1()  asm volatile("cp.async.wait_group 1;" ::: "memory")

// =====================================================================
// Logits GEMM: C[256, 32003] = A[256,1024] @ B[32003,1024]^T + bias
// Single-term fp16 mma.sync (norm rel-err ~2e-4 << 1e-3).
// CTA tile 128x128, 8 warps (2x4), warp tile 64x32, K-chunk 32.
// Per buffer: A plane + B plane, 128 rows x pitch-24 words (16 data: fp16
// k-pairs interleaved (k,k+1)/(k+8,k+9), XOR quad swizzle on row bit2).
// STS.128 and LDS.64 both bank-conflict-free. 2 CTAs/SM.
// =====================================================================
#define LP    24
#define PLANE (128 * LP)        // 3072 words
#define BUFW  (2 * PLANE)       // 6144 words
#define LG_SMEM_BYTES (2 * BUFW * 4)   // 49152

__global__ void __launch_bounds__(256, 2)
logits_f16(const float* __restrict__ A, const float* __restrict__ Bw,
           const float* __restrict__ bias, float* __restrict__ C)
{
    extern __shared__ uint32_t sm[];
    const int t    = threadIdx.x;
    const int lane = t & 31;
    const int wid  = t >> 5;
    const int wm   = wid >> 2;
    const int wn   = wid & 3;
    const int bm   = blockIdx.x & 1;
    const int bn   = blockIdx.x >> 1;

    // producer: one thread per smem row
    const bool isA = t < 128;
    const int  row = isA ? t : t - 128;
    const float* gsrc;
    if (isA) {
        gsrc = A + (size_t)(bm * 128 + row) * DIM;
    } else {
        int ng = bn * 128 + row;
        if (ng > VOCAB - 1) ng = VOCAB - 1;
        gsrc = Bw + (size_t)ng * DIM;
    }
    const int bp = (row >> 2) & 1;
    uint32_t* myrow = sm + (isA ? 0 : PLANE) + row * LP;

    uint4 W[4];
    auto ldcvt = [&](int ch) {
        const float4* p = (const float4*)(gsrc + ch * 32);
        float4 v0 = p[0], v1 = p[1], v2 = p[2], v3 = p[3];
        W[0] = packq(v0, v2);
        W[1] = packq(v1, v3);
        v0 = p[4]; v1 = p[5]; v2 = p[6]; v3 = p[7];
        W[2] = packq(v0, v2);
        W[3] = packq(v1, v3);
    };
    auto stq = [&](int buf) {
        uint32_t* b_ = myrow + buf * BUFW;
        *(uint4*)(b_ + 4 * (0 ^ bp))     = W[0];
        *(uint4*)(b_ + 4 * (1 ^ bp))     = W[1];
        *(uint4*)(b_ + 8 + 4 * (0 ^ bp)) = W[2];
        *(uint4*)(b_ + 8 + 4 * (1 ^ bp)) = W[3];
    };

    float acc[4][4][4];
#pragma unroll
    for (int i = 0; i < 4; i++)
#pragma unroll
        for (int j = 0; j < 4; j++)
#pragma unroll
            for (int k = 0; k < 4; k++) acc[i][j][k] = 0.f;

    // consumer constants
    const int c_ = lane & 3;
    const int bt = (lane >> 4) & 1;
    const int cs = 4 * ((c_ >> 1) ^ bt) + 2 * (c_ & 1);
    const int rA = wm * 64 + (lane >> 2);
    const int cB = wn * 32 + (lane >> 2);

    ldcvt(0);
    stq(0);
    ldcvt(1);
    __syncthreads();

    const int NCHUNK = DIM / 32;   // 32
    for (int ch = 0; ch < NCHUNK; ch++) {
        if (ch + 1 < NCHUNK) stq((ch + 1) & 1);   // other buffer than MMA reads
        if (ch + 2 < NCHUNK) ldcvt(ch + 2);

        const uint32_t* Ab = sm + (ch & 1) * BUFW;
        const uint32_t* Bb = Ab + PLANE;
#pragma unroll
        for (int h = 0; h < 2; h++) {
            const int off = 8 * h + cs;
            uint2 af[4][2];
#pragma unroll
            for (int mt = 0; mt < 4; mt++) {
                af[mt][0] = *(const uint2*)(Ab + (rA + 16 * mt) * LP + off);
                af[mt][1] = *(const uint2*)(Ab + (rA + 16 * mt + 8) * LP + off);
            }
#pragma unroll
            for (int nt = 0; nt < 4; nt++) {
                uint2 bf = *(const uint2*)(Bb + (cB + 8 * nt) * LP + off);
#pragma unroll
                for (int mt = 0; mt < 4; mt++)
                    mmaf16(acc[mt][nt], af[mt][0].x, af[mt][1].x,
                           af[mt][0].y, af[mt][1].y, bf.x, bf.y);
            }
        }
        __syncthreads();
    }

    // epilogue: guarded scalar stores (VOCAB odd -> no float2 alignment)
    const int n0 = bn * 128 + wn * 32 + 2 * c_;
    float bz[8];
#pragma unroll
    for (int nt = 0; nt < 4; nt++) {
        int n = n0 + 8 * nt;
        bz[2 * nt]     = (n     < VOCAB) ? bias[n]     : 0.f;
        bz[2 * nt + 1] = (n + 1 < VOCAB) ? bias[n + 1] : 0.f;
    }
    const int m0 = bm * 128 + wm * 64 + (lane >> 2);
#pragma unroll
    for (int mt = 0; mt < 4; mt++) {
        float* r0 = C + (size_t)(m0 + 16 * mt) * VOCAB;
        float* r1 = r0 + (size_t)8 * VOCAB;
#pragma unroll
        for (int nt = 0; nt < 4; nt++) {
            int n = n0 + 8 * nt;
            if (n < VOCAB) {
                r0[n] = acc[mt][nt][0] + bz[2 * nt];
                r1[n] = acc[mt][nt][2] + bz[2 * nt];
            }
            if (n + 1 < VOCAB) {
                r0[n + 1] = acc[mt][nt][1] + bz[2 * nt + 1];
                r1[n + 1] = acc[mt][nt][3] + bz[2 * nt + 1];
            }
        }
    }
}

// =====================================================================
// 64x64 FFMA2 GEMM for the small GEMMs (gi0, gi1, preout)
// =====================================================================
template<int ACT>
__global__ void __launch_bounds__(256)
gemm64(int N, int K,
       const float* __restrict__ A, int lda,
       const float* __restrict__ Bw, int ldb,
       float* __restrict__ C, int ldc,
       const float* __restrict__ bias,
       const int* __restrict__ gather)
{
    __shared__ float As[16][64];
    __shared__ float Bs[16][64];
    const int bm = blockIdx.y * 64;
    const int bn = blockIdx.x * 64;
    const int tid = threadIdx.x;
    const int tx = tid & 15, ty = tid >> 4;

    unsigned long long acc[4][2];
#pragma unroll
    for (int i = 0; i < 4; i++) { acc[i][0] = 0ULL; acc[i][1] = 0ULL; }

    for (int k0 = 0; k0 < K; k0 += 16) {
        {
            int r  = tid >> 2;
            int c4 = (tid & 3) << 2;
            int row  = bm + r;
            int arow = gather ? gather[row] : row;
            float4 v = *(const float4*)(A + (size_t)arow * lda + k0 + c4);
            As[c4+0][r] = v.x; As[c4+1][r] = v.y; As[c4+2][r] = v.z; As[c4+3][r] = v.w;
            int rowb = bn + r;
            float4 w = make_float4(0.f, 0.f, 0.f, 0.f);
            if (rowb < N) w = *(const float4*)(Bw + (size_t)rowb * ldb + k0 + c4);
            Bs[c4+0][r] = w.x; Bs[c4+1][r] = w.y; Bs[c4+2][r] = w.z; Bs[c4+3][r] = w.w;
        }
        __syncthreads();
#pragma unroll
        for (int k = 0; k < 16; k++) {
            float4 a = *(const float4*)&As[k][ty * 4];
            ulonglong2 b = *(const ulonglong2*)&Bs[k][tx * 4];
            unsigned long long av[4] = {dup2(a.x), dup2(a.y), dup2(a.z), dup2(a.w)};
#pragma unroll
            for (int i = 0; i < 4; i++) {
                fma2(acc[i][0], av[i], b.x);
                fma2(acc[i][1], av[i], b.y);
            }
        }
        __syncthreads();
    }

#pragma unroll
    for (int i = 0; i < 4; i++) {
        int m = bm + ty * 4 + i;
        float* crow = C + (size_t)m * ldc;
#pragma unroll
        for (int j = 0; j < 2; j++) {
            int n = bn + tx * 4 + j * 2;
            F2U v; v.u = acc[i][j];
            if (n < N) {
                float x = v.f.x + bias[n];
                crow[n] = ACT ? celu1(x) : x;
            }
            if (n + 1 < N) {
                float x = v.f.y + bias[n + 1];
                crow[n + 1] = ACT ? celu1(x) : x;
            }
        }
    }
}

// =====================================================================
// GRU gates (zero previous hidden state): h' = (1-z) * n
// =====================================================================
__global__ void gru_gates(const float* __restrict__ gi, const float* __restrict__ bhh,
                          float* __restrict__ h, int ldh)
{
    int idx = blockIdx.x * blockDim.x + threadIdx.x;
    int b = idx >> 10, d = idx & 1023;
    const float* g = gi + (size_t)b * (3 * DIM);
    float r = 1.f / (1.f + expf(-(g[d]           + bhh[d])));
    float z = 1.f / (1.f + expf(-(g[DIM + d]     + bhh[DIM + d])));
    float n = tanhf(g[2 * DIM + d] + r * bhh[2 * DIM + d]);
    h[(size_t)b * ldh + d] = (1.f - z) * n;
}

// =====================================================================
// Fused single-query attention, online softmax, cp.async double-buffered.
// One block per batch row; smem = h1 (4KB) + 2 x 8-row tile (64KB).
// =====================================================================
#define ATTN_SMEM_BYTES ((1024 + 2 * 8 * 1024 + 8) * 4)

__global__ void __launch_bounds__(256)
attn_kernel(const float* __restrict__ enc, const int* __restrict__ mask,
            float* __restrict__ cat)
{
    extern __shared__ float smf[];
    float* h1s   = smf;                  // 1024
    float* tiles = smf + 1024;           // 2 * 8192
    float* wsh   = smf + 1024 + 16384;   // 8

    const int b   = blockIdx.x;
    const int tid = threadIdx.x;
    const float* h1 = cat + (size_t)b * (2 * DIM);
    const float* encb  = enc  + (size_t)b * SEQ * DIM;
    const int*   maskb = mask + b * SEQ;

    ((float4*)h1s)[tid] = ((const float4*)h1)[tid];

    const uint32_t tbase = (uint32_t)__cvta_generic_to_shared(tiles);
    auto issue = [&](int it) {
        const float* src = encb + (size_t)it * 8 * DIM + tid * 4;
        uint32_t dst = tbase + (uint32_t)((it & 1) * 32768 + tid * 16);
#pragma unroll
        for (int i = 0; i < 8; i++)
            CP_ASYNC16(dst + i * 4096, (const void*)(src + i * 1024));
    };

    issue(0); CP_COMMIT();
    issue(1); CP_COMMIT();

    float m = -1e30f, l = 0.f;
    float4 acc = make_float4(0.f, 0.f, 0.f, 0.f);

    for (int it = 0; it < SEQ / 8; it++) {
        CP_WAIT1();
        __syncthreads();
        const float* tb = tiles + (it & 1) * 8192;

        {
            int w = tid >> 5, lane = tid & 31;
            float p = 0.f;
            const float4* er = (const float4*)(tb + w * 1024);
            const float4* hr = (const float4*)h1s;
#pragma unroll
            for (int i = 0; i < 8; i++) {
                float4 e  = er[lane + i * 32];
                float4 hv = hr[lane + i * 32];
                p += e.x * hv.x + e.y * hv.y + e.z * hv.z + e.w * hv.w;
            }
#pragma unroll
            for (int off = 16; off; off >>= 1) p += __shfl_xor_sync(0xffffffffu, p, off);
            if (lane == 0) wsh[w] = maskb[it * 8 + w] ? p : -1e30f;
        }
        __syncthreads();

        float wv[8];
        float tm = -1e30f;
#pragma unroll
        for (int j = 0; j < 8; j++) { wv[j] = wsh[j]; tm = fmaxf(tm, wv[j]); }
        float mnew  = fmaxf(m, tm);
        float scale = __expf(m - mnew);
        l *= scale;
        acc.x *= scale; acc.y *= scale; acc.z *= scale; acc.w *= scale;
#pragma unroll
        for (int j = 0; j < 8; j++) {
            float pj = __expf(wv[j] - mnew);
            l += pj;
            float4 e = *(const float4*)(tb + j * 1024 + tid * 4);
            acc.x += pj * e.x; acc.y += pj * e.y; acc.z += pj * e.z; acc.w += pj * e.w;
        }
        m = mnew;
        __syncthreads();   // all reads of this buffer done before refill

        if (it + 2 < SEQ / 8) issue(it + 2);
        CP_COMMIT();
    }

    float inv = 1.f / l;
    float4 o = make_float4(acc.x * inv, acc.y * inv, acc.z * inv, acc.w * inv);
    *(float4*)(cat + (size_t)b * (2 * DIM) + DIM + tid * 4) = o;
}

// =====================================================================
// launcher
// =====================================================================
extern "C" void kernel_launch(void* const* d_in, const int* in_sizes, int n_in,
                              void* d_out, int out_size)
{
    (void)in_sizes; (void)n_in; (void)out_size;
    const int*   tokens   = (const int*)  d_in[0];
    const float* enc      = (const float*)d_in[1];
    const int*   encmask  = (const int*)  d_in[2];
    const float* dec_emb  = (const float*)d_in[3];
    const float* Wih0     = (const float*)d_in[4];
    const float* bih0     = (const float*)d_in[6];
    const float* bhh0     = (const float*)d_in[7];
    const float* Wih1     = (const float*)d_in[8];
    const float* bih1     = (const float*)d_in[10];
    const float* bhh1     = (const float*)d_in[11];
    const float* preout_w = (const float*)d_in[12];
    const float* preout_b = (const float*)d_in[13];
    const float* out_w    = (const float*)d_in[14];
    const float* out_b    = (const float*)d_in[15];
    float* logits = (float*)d_out;

    float *gi, *h0, *cat, *pre;
    cudaGetSymbolAddress((void**)&gi,  g_gi);
    cudaGetSymbolAddress((void**)&h0,  g_h0);
    cudaGetSymbolAddress((void**)&cat, g_cat);
    cudaGetSymbolAddress((void**)&pre, g_pre);

    static int smem_set = 0;
    if (!smem_set) {
        cudaFuncSetAttribute(logits_f16, cudaFuncAttributeMaxDynamicSharedMemorySize, LG_SMEM_BYTES);
        cudaFuncSetAttribute(attn_kernel, cudaFuncAttributeMaxDynamicSharedMemorySize, ATTN_SMEM_BYTES);
        smem_set = 1;
    }

    // 1) gi0 = dec_emb[tokens] @ Wih0[:, :D]^T + bih0
    gemm64<0><<<dim3(3 * DIM / 64, BATCH / 64), 256>>>(
        3 * DIM, DIM, dec_emb, DIM, Wih0, 2 * DIM, gi, 3 * DIM, bih0, tokens);

    // 2) h0
    gru_gates<<<(BATCH * DIM) / 256, 256>>>(gi, bhh0, h0, DIM);

    // 3) gi1 = h0 @ Wih1^T + bih1
    gemm64<0><<<dim3(3 * DIM / 64, BATCH / 64), 256>>>(
        3 * DIM, DIM, h0, DIM, Wih1, DIM, gi, 3 * DIM, bih1, nullptr);

    // 4) h1 -> cat[:, 0:D]
    gru_gates<<<(BATCH * DIM) / 256, 256>>>(gi, bhh1, cat, 2 * DIM);

    // 5) attention summary -> cat[:, D:2D]
    attn_kernel<<<BATCH, 256, ATTN_SMEM_BYTES>>>(enc, encmask, cat);

    // 6) pre = celu(cat @ preout_w^T + preout_b)
    gemm64<1><<<dim3(DIM / 64, BATCH / 64), 256>>>(
        DIM, 2 * DIM, cat, 2 * DIM, preout_w, 2 * DIM, pre, DIM, preout_b, nullptr);

    // 7) logits = pre @ out_w^T + out_b   (single-term fp16 mma.sync)
    logits_f16<<<((VOCAB + 127) / 128) * 2, 256, LG_SMEM_BYTES>>>(pre, out_w, out_b, logits);
}

// round 7
// speedup vs baseline: 1.5821x; 1.1593x over previous
#include <cuda_runtime.h>
#include <cuda_fp16.h>
#include <cstdint>
#include <math.h>

#define BATCH 256
#define SEQ   512
#define DIM   1024
#define VOCAB 32003

// ---------------- scratch (static device globals; no allocation) ----------------
__device__ float g_gi[BATCH * 3 * DIM];
__device__ float g_h0[BATCH * DIM];
__device__ float g_cat[BATCH * 2 * DIM];
__device__ float g_pre[BATCH * DIM];
__device__ uint32_t g_Apack[BATCH * (DIM / 2)];   // pre-swizzled fp16 A for logits

// ---------------- packed fp32x2 helpers (FFMA2) ----------------
__device__ __forceinline__ unsigned long long dup2(float x) {
    unsigned long long r;
    asm("mov.b64 %0, {%1, %1};" : "=l"(r) : "r"(__float_as_uint(x)));
    return r;
}
__device__ __forceinline__ void fma2(unsigned long long& d, unsigned long long a, unsigned long long b) {
    asm("fma.rn.f32x2 %0, %1, %2, %0;" : "+l"(d) : "l"(a), "l"(b));
}
union F2U { unsigned long long u; float2 f; };

__device__ __forceinline__ float celu1(float x) { return x > 0.f ? x : expm1f(x); }

// ---------------- fp16 helpers ----------------
__device__ __forceinline__ uint32_t h2pack(float x, float y) {
    __half2 h = __floats2half2_rn(x, y);
    return *(uint32_t*)&h;
}
__device__ __forceinline__ uint4 packq(float4 x, float4 y) {
    uint4 w;
    w.x = h2pack(x.x, x.y);
    w.y = h2pack(y.x, y.y);
    w.z = h2pack(x.z, x.w);
    w.w = h2pack(y.z, y.w);
    return w;
}
__device__ __forceinline__ void mmaf16(float* c, uint32_t a0, uint32_t a1, uint32_t a2,
                                       uint32_t a3, uint32_t b0, uint32_t b1) {
    asm volatile("mma.sync.aligned.m16n8k16.row.col.f32.f16.f16.f32 "
                 "{%0,%1,%2,%3}, {%4,%5,%6,%7}, {%8,%9}, {%0,%1,%2,%3};"
                 : "+f"(c[0]), "+f"(c[1]), "+f"(c[2]), "+f"(c[3])
                 : "r"(a0), "r"(a1), "r"(a2), "r"(a3), "r"(b0), "r"(b1));
}

// ---------------- cp.async helpers ----------------
#define CP_ASYNC16(dst, src) \
    asm volatile("cp.async.cg.shared.global [%0], [%1], 16;" :: "r"(dst), "l"(src))
#define CP_COMMIT() asm volatile("cp.async.commit_group;" ::: "memory")
#define CP_WAIT0()  asm volatile("cp.async.wait_group 0;" ::: "memory")
#define CP_WAIT1()  asm volatile("cp.async.wait_group 1;" ::: "memory")

// =====================================================================
// Pre-pack A (= pre, 256x1024 fp32) into the swizzled fp16 tile layout.
// Per (row, chunk of 32 k): 16 words; halves at word 8*half, quads
// XOR-swizzled by bp=(row>>2)&1 and by half.
// =====================================================================
__global__ void __launch_bounds__(256)
prepackA(const float* __restrict__ A, uint32_t* __restrict__ out)
{
    int idx = blockIdx.x * 256 + threadIdx.x;     // 8192 = 256 rows x 32 chunks
    int row = idx >> 5, ch = idx & 31;
    const float4* p = (const float4*)(A + (size_t)row * DIM + ch * 32);
    float4 p0 = p[0], p1 = p[1], p2 = p[2], p3 = p[3];
    float4 p4 = p[4], p5 = p[5], p6 = p[6], p7 = p[7];
    int bp = (row >> 2) & 1;
    uint32_t* o = out + (size_t)row * (DIM / 2) + ch * 16;
    // half 0: quad (q^bp)
    *(uint4*)(o + 4 * bp)       = packq(p0, p2);
    *(uint4*)(o + 4 * (bp ^ 1)) = packq(p1, p3);
    // half 1: quad (q^bp^1)
    *(uint4*)(o + 8 + 4 * (bp ^ 1)) = packq(p4, p6);
    *(uint4*)(o + 8 + 4 * bp)       = packq(p5, p7);
}

// =====================================================================
// Logits GEMM: C[256, 32003] = A[256,1024] @ B[32003,1024]^T + bias
// fp16 mma.sync. CTA tile 128x128, 8 warps (2x4), warp tile 64x32, K=32/chunk.
// A plane filled by cp.async from g_Apack (pre-swizzled); B converted by
// 2 threads/row. Pitch 24, double buffer, 1 sync/chunk, 2 CTAs/SM.
// =====================================================================
#define LP    24
#define PLANE (128 * LP)        // 3072 words
#define BUFW  (2 * PLANE)       // 6144 words
#define LG_SMEM_BYTES (2 * BUFW * 4)   // 49152

__global__ void __launch_bounds__(256, 2)
logits_f16(const uint32_t* __restrict__ Apack, const float* __restrict__ Bw,
           const float* __restrict__ bias, float* __restrict__ C)
{
    extern __shared__ uint32_t sm[];
    const uint32_t smb = (uint32_t)__cvta_generic_to_shared(sm);
    const int t    = threadIdx.x;
    const int lane = t & 31;
    const int wid  = t >> 5;
    const int wm   = wid >> 2;
    const int wn   = wid & 3;
    const int bm   = blockIdx.x & 1;
    const int bn   = blockIdx.x >> 1;

    // ---- producer setup ----
    const int rb   = t >> 1;          // B row in tile (2 threads/row)
    const int half = t & 1;           // which 16-k half
    const int bpB  = (rb >> 2) & 1;
    int ng = bn * 128 + rb;
    if (ng > VOCAB - 1) ng = VOCAB - 1;
    const float* gsrcB = Bw + (size_t)ng * DIM + half * 16;
    // B store word offsets within row: 8*half + 4*((q^bp)^half)
    const int wq0 = 8 * half + 4 * (bpB ^ half);
    const int wq1 = 8 * half + 4 * ((bpB ^ 1) ^ half);
    // A cp.async: thread copies 2x16B of row (t>>1), words (t&1)*8 .. +7
    const uint32_t* srcA = Apack + (size_t)(bm * 128 + rb) * (DIM / 2) + half * 8;
    const uint32_t dstA_row = (uint32_t)(rb * LP + half * 8) * 4;

    float4 pf[4];
    auto ldB = [&](int ch) {
        const float4* p = (const float4*)(gsrcB + ch * 32);
        pf[0] = p[0]; pf[1] = p[1]; pf[2] = p[2]; pf[3] = p[3];
    };
    auto stB = [&](int buf) {
        uint32_t* base = sm + buf * BUFW + PLANE + rb * LP;
        *(uint4*)(base + wq0) = packq(pf[0], pf[2]);
        *(uint4*)(base + wq1) = packq(pf[1], pf[3]);
    };
    auto issueA = [&](int ch, int buf) {
        uint32_t d = smb + (uint32_t)buf * BUFW * 4 + dstA_row;
        const uint32_t* s = srcA + ch * 16;
        CP_ASYNC16(d, s);
        CP_ASYNC16(d + 16, s + 4);
    };

    float acc[4][4][4];
#pragma unroll
    for (int i = 0; i < 4; i++)
#pragma unroll
        for (int j = 0; j < 4; j++)
#pragma unroll
            for (int k = 0; k < 4; k++) acc[i][j][k] = 0.f;

    // consumer constants
    const int c_ = lane & 3;
    const int bt = (lane >> 4) & 1;
    const int q2 = (c_ >> 1) ^ bt;
    const int rA = wm * 64 + (lane >> 2);
    const int cB = wn * 32 + (lane >> 2);

    // prologue
    issueA(0, 0); CP_COMMIT();
    ldB(0); stB(0);
    ldB(1);
    CP_WAIT0();
    __syncthreads();

    const int NCHUNK = DIM / 32;   // 32
    for (int ch = 0; ch < NCHUNK; ch++) {
        const int wb = (ch + 1) & 1;
        if (ch + 1 < NCHUNK) {
            issueA(ch + 1, wb); CP_COMMIT();
            stB(wb);
        }
        if (ch + 2 < NCHUNK) ldB(ch + 2);

        const uint32_t* Ab = sm + (ch & 1) * BUFW;
        const uint32_t* Bb = Ab + PLANE;
#pragma unroll
        for (int h = 0; h < 2; h++) {
            const int off = 8 * h + 4 * (q2 ^ h) + 2 * (c_ & 1);
            uint2 af[4][2];
#pragma unroll
            for (int mt = 0; mt < 4; mt++) {
                af[mt][0] = *(const uint2*)(Ab + (rA + 16 * mt) * LP + off);
                af[mt][1] = *(const uint2*)(Ab + (rA + 16 * mt + 8) * LP + off);
            }
#pragma unroll
            for (int nt = 0; nt < 4; nt++) {
                uint2 bf = *(const uint2*)(Bb + (cB + 8 * nt) * LP + off);
#pragma unroll
                for (int mt = 0; mt < 4; mt++)
                    mmaf16(acc[mt][nt], af[mt][0].x, af[mt][1].x,
                           af[mt][0].y, af[mt][1].y, bf.x, bf.y);
            }
        }
        if (ch + 1 < NCHUNK) CP_WAIT0();
        __syncthreads();
    }

    // epilogue: guarded scalar stores (VOCAB odd)
    const int n0 = bn * 128 + wn * 32 + 2 * c_;
    float bz[8];
#pragma unroll
    for (int nt = 0; nt < 4; nt++) {
        int n = n0 + 8 * nt;
        bz[2 * nt]     = (n     < VOCAB) ? bias[n]     : 0.f;
        bz[2 * nt + 1] = (n + 1 < VOCAB) ? bias[n + 1] : 0.f;
    }
    const int m0 = bm * 128 + wm * 64 + (lane >> 2);
#pragma unroll
    for (int mt = 0; mt < 4; mt++) {
        float* r0 = C + (size_t)(m0 + 16 * mt) * VOCAB;
        float* r1 = r0 + (size_t)8 * VOCAB;
#pragma unroll
        for (int nt = 0; nt < 4; nt++) {
            int n = n0 + 8 * nt;
            if (n < VOCAB) {
                r0[n] = acc[mt][nt][0] + bz[2 * nt];
                r1[n] = acc[mt][nt][2] + bz[2 * nt];
            }
            if (n + 1 < VOCAB) {
                r0[n + 1] = acc[mt][nt][1] + bz[2 * nt + 1];
                r1[n + 1] = acc[mt][nt][3] + bz[2 * nt + 1];
            }
        }
    }
}

// =====================================================================
// 64x64 FFMA2 GEMM for the small GEMMs (gi0, gi1, preout)
// =====================================================================
template<int ACT>
__global__ void __launch_bounds__(256)
gemm64(int N, int K,
       const float* __restrict__ A, int lda,
       const float* __restrict__ Bw, int ldb,
       float* __restrict__ C, int ldc,
       const float* __restrict__ bias,
       const int* __restrict__ gather)
{
    __shared__ float As[16][64];
    __shared__ float Bs[16][64];
    const int bm = blockIdx.y * 64;
    const int bn = blockIdx.x * 64;
    const int tid = threadIdx.x;
    const int tx = tid & 15, ty = tid >> 4;

    unsigned long long acc[4][2];
#pragma unroll
    for (int i = 0; i < 4; i++) { acc[i][0] = 0ULL; acc[i][1] = 0ULL; }

    for (int k0 = 0; k0 < K; k0 += 16) {
        {
            int r  = tid >> 2;
            int c4 = (tid & 3) << 2;
            int row  = bm + r;
            int arow = gather ? gather[row] : row;
            float4 v = *(const float4*)(A + (size_t)arow * lda + k0 + c4);
            As[c4+0][r] = v.x; As[c4+1][r] = v.y; As[c4+2][r] = v.z; As[c4+3][r] = v.w;
            int rowb = bn + r;
            float4 w = make_float4(0.f, 0.f, 0.f, 0.f);
            if (rowb < N) w = *(const float4*)(Bw + (size_t)rowb * ldb + k0 + c4);
            Bs[c4+0][r] = w.x; Bs[c4+1][r] = w.y; Bs[c4+2][r] = w.z; Bs[c4+3][r] = w.w;
        }
        __syncthreads();
#pragma unroll
        for (int k = 0; k < 16; k++) {
            float4 a = *(const float4*)&As[k][ty * 4];
            ulonglong2 b = *(const ulonglong2*)&Bs[k][tx * 4];
            unsigned long long av[4] = {dup2(a.x), dup2(a.y), dup2(a.z), dup2(a.w)};
#pragma unroll
            for (int i = 0; i < 4; i++) {
                fma2(acc[i][0], av[i], b.x);
                fma2(acc[i][1], av[i], b.y);
            }
        }
        __syncthreads();
    }

#pragma unroll
    for (int i = 0; i < 4; i++) {
        int m = bm + ty * 4 + i;
        float* crow = C + (size_t)m * ldc;
#pragma unroll
        for (int j = 0; j < 2; j++) {
            int n = bn + tx * 4 + j * 2;
            F2U v; v.u = acc[i][j];
            if (n < N) {
                float x = v.f.x + bias[n];
                crow[n] = ACT ? celu1(x) : x;
            }
            if (n + 1 < N) {
                float x = v.f.y + bias[n + 1];
                crow[n + 1] = ACT ? celu1(x) : x;
            }
        }
    }
}

// =====================================================================
// GRU gates (zero previous hidden state): h' = (1-z) * n   (layer 0 only)
// =====================================================================
__global__ void gru_gates(const float* __restrict__ gi, const float* __restrict__ bhh,
                          float* __restrict__ h, int ldh)
{
    int idx = blockIdx.x * blockDim.x + threadIdx.x;
    int b = idx >> 10, d = idx & 1023;
    const float* g = gi + (size_t)b * (3 * DIM);
    float r = 1.f / (1.f + expf(-(g[d]           + bhh[d])));
    float z = 1.f / (1.f + expf(-(g[DIM + d]     + bhh[DIM + d])));
    float n = tanhf(g[2 * DIM + d] + r * bhh[2 * DIM + d]);
    h[(size_t)b * ldh + d] = (1.f - z) * n;
}

// =====================================================================
// Fused attention: computes h1 = gates(gi1, bhh1) in-block, writes h1 to
// cat[:,0:D], online-softmax summary to cat[:,D:2D]. Mask preloaded to smem.
// cp.async double-buffered enc tiles. One block per batch row.
// =====================================================================
#define ATTN_SMEM_BYTES ((1024 + 2 * 8 * 1024 + 8 + 512) * 4)

__global__ void __launch_bounds__(256)
attn_kernel(const float* __restrict__ enc, const int* __restrict__ mask,
            const float* __restrict__ gi, const float* __restrict__ bhh,
            float* __restrict__ cat)
{
    extern __shared__ float smf[];
    float* h1s   = smf;                          // 1024
    float* tiles = smf + 1024;                   // 2 * 8192
    float* wsh   = smf + 1024 + 16384;           // 8
    int*   msk   = (int*)(smf + 1024 + 16384 + 8);  // 512

    const int b   = blockIdx.x;
    const int tid = threadIdx.x;
    const float* encb  = enc  + (size_t)b * SEQ * DIM;
    const int*   maskb = mask + b * SEQ;

    // mask preload
    msk[tid]       = maskb[tid];
    msk[tid + 256] = maskb[tid + 256];

    // h1 gates (4 elements per thread)
    {
        const float* g = gi + (size_t)b * (3 * DIM);
        int d = tid * 4;
        float4 vr = *(const float4*)(g + d);
        float4 vz = *(const float4*)(g + DIM + d);
        float4 vn = *(const float4*)(g + 2 * DIM + d);
        float4 br = *(const float4*)(bhh + d);
        float4 bz = *(const float4*)(bhh + DIM + d);
        float4 bn = *(const float4*)(bhh + 2 * DIM + d);
        float h[4];
        {
            float r0 = 1.f / (1.f + expf(-(vr.x + br.x)));
            float z0 = 1.f / (1.f + expf(-(vz.x + bz.x)));
            h[0] = (1.f - z0) * tanhf(vn.x + r0 * bn.x);
            float r1 = 1.f / (1.f + expf(-(vr.y + br.y)));
            float z1 = 1.f / (1.f + expf(-(vz.y + bz.y)));
            h[1] = (1.f - z1) * tanhf(vn.y + r1 * bn.y);
            float r2 = 1.f / (1.f + expf(-(vr.z + br.z)));
            float z2 = 1.f / (1.f + expf(-(vz.z + bz.z)));
            h[2] = (1.f - z2) * tanhf(vn.z + r2 * bn.z);
            float r3 = 1.f / (1.f + expf(-(vr.w + br.w)));
            float z3 = 1.f / (1.f + expf(-(vz.w + bz.w)));
            h[3] = (1.f - z3) * tanhf(vn.w + r3 * bn.w);
        }
        float4 hv = make_float4(h[0], h[1], h[2], h[3]);
        *(float4*)(h1s + d) = hv;
        *(float4*)(cat + (size_t)b * (2 * DIM) + d) = hv;
    }

    const uint32_t tbase = (uint32_t)__cvta_generic_to_shared(tiles);
    auto issue = [&](int it) {
        const float* src = encb + (size_t)it * 8 * DIM + tid * 4;
        uint32_t dst = tbase + (uint32_t)((it & 1) * 32768 + tid * 16);
#pragma unroll
        for (int i = 0; i < 8; i++)
            CP_ASYNC16(dst + i * 4096, (const void*)(src + i * 1024));
    };

    issue(0); CP_COMMIT();
    issue(1); CP_COMMIT();

    float m = -1e30f, l = 0.f;
    float4 acc = make_float4(0.f, 0.f, 0.f, 0.f);

    for (int it = 0; it < SEQ / 8; it++) {
        CP_WAIT1();
        __syncthreads();
        const float* tb = tiles + (it & 1) * 8192;

        {
            int w = tid >> 5, lane = tid & 31;
            float p = 0.f;
            const float4* er = (const float4*)(tb + w * 1024);
            const float4* hr = (const float4*)h1s;
#pragma unroll
            for (int i = 0; i < 8; i++) {
                float4 e  = er[lane + i * 32];
                float4 hv = hr[lane + i * 32];
                p += e.x * hv.x + e.y * hv.y + e.z * hv.z + e.w * hv.w;
            }
#pragma unroll
            for (int off = 16; off; off >>= 1) p += __shfl_xor_sync(0xffffffffu, p, off);
            if (lane == 0) wsh[w] = msk[it * 8 + w] ? p : -1e30f;
        }
        __syncthreads();

        float wv[8];
        float tm = -1e30f;
#pragma unroll
        for (int j = 0; j < 8; j++) { wv[j] = wsh[j]; tm = fmaxf(tm, wv[j]); }
        float mnew  = fmaxf(m, tm);
        float scale = __expf(m - mnew);
        l *= scale;
        acc.x *= scale; acc.y *= scale; acc.z *= scale; acc.w *= scale;
#pragma unroll
        for (int j = 0; j < 8; j++) {
            float pj = __expf(wv[j] - mnew);
            l += pj;
            float4 e = *(const float4*)(tb + j * 1024 + tid * 4);
            acc.x += pj * e.x; acc.y += pj * e.y; acc.z += pj * e.z; acc.w += pj * e.w;
        }
        m = mnew;
        __syncthreads();

        if (it + 2 < SEQ / 8) issue(it + 2);
        CP_COMMIT();
    }

    float inv = 1.f / l;
    float4 o = make_float4(acc.x * inv, acc.y * inv, acc.z * inv, acc.w * inv);
    *(float4*)(cat + (size_t)b * (2 * DIM) + DIM + tid * 4) = o;
}

// =====================================================================
// launcher
// =====================================================================
extern "C" void kernel_launch(void* const* d_in, const int* in_sizes, int n_in,
                              void* d_out, int out_size)
{
    (void)in_sizes; (void)n_in; (void)out_size;
    const int*   tokens   = (const int*)  d_in[0];
    const float* enc      = (const float*)d_in[1];
    const int*   encmask  = (const int*)  d_in[2];
    const float* dec_emb  = (const float*)d_in[3];
    const float* Wih0     = (const float*)d_in[4];
    const float* bih0     = (const float*)d_in[6];
    const float* bhh0     = (const float*)d_in[7];
    const float* Wih1     = (const float*)d_in[8];
    const float* bih1     = (const float*)d_in[10];
    const float* bhh1     = (const float*)d_in[11];
    const float* preout_w = (const float*)d_in[12];
    const float* preout_b = (const float*)d_in[13];
    const float* out_w    = (const float*)d_in[14];
    const float* out_b    = (const float*)d_in[15];
    float* logits = (float*)d_out;

    float *gi, *h0, *cat, *pre;
    uint32_t* apack;
    cudaGetSymbolAddress((void**)&gi,    g_gi);
    cudaGetSymbolAddress((void**)&h0,    g_h0);
    cudaGetSymbolAddress((void**)&cat,   g_cat);
    cudaGetSymbolAddress((void**)&pre,   g_pre);
    cudaGetSymbolAddress((void**)&apack, g_Apack);

    static int smem_set = 0;
    if (!smem_set) {
        cudaFuncSetAttribute(logits_f16, cudaFuncAttributeMaxDynamicSharedMemorySize, LG_SMEM_BYTES);
        cudaFuncSetAttribute(attn_kernel, cudaFuncAttributeMaxDynamicSharedMemorySize, ATTN_SMEM_BYTES);
        smem_set = 1;
    }

    // 1) gi0 = dec_emb[tokens] @ Wih0[:, :D]^T + bih0
    gemm64<0><<<dim3(3 * DIM / 64, BATCH / 64), 256>>>(
        3 * DIM, DIM, dec_emb, DIM, Wih0, 2 * DIM, gi, 3 * DIM, bih0, tokens);

    // 2) h0
    gru_gates<<<(BATCH * DIM) / 256, 256>>>(gi, bhh0, h0, DIM);

    // 3) gi1 = h0 @ Wih1^T + bih1
    gemm64<0><<<dim3(3 * DIM / 64, BATCH / 64), 256>>>(
        3 * DIM, DIM, h0, DIM, Wih1, DIM, gi, 3 * DIM, bih1, nullptr);

    // 4) fused: h1 gates + attention summary -> cat
    attn_kernel<<<BATCH, 256, ATTN_SMEM_BYTES>>>(enc, encmask, gi, bhh1, cat);

    // 5) pre = celu(cat @ preout_w^T + preout_b)
    gemm64<1><<<dim3(DIM / 64, BATCH / 64), 256>>>(
        DIM, 2 * DIM, cat, 2 * DIM, preout_w, 2 * DIM, pre, DIM, preout_b, nullptr);

    // 6) pre-pack A for logits (fp16 swizzled layout)
    prepackA<<<32, 256>>>(pre, apack);

    // 7) logits = Apack @ out_w^T + out_b   (fp16 mma.sync, cp.async A)
    logits_f16<<<((VOCAB + 127) / 128) * 2, 256, LG_SMEM_BYTES>>>(apack, out_w, out_b, logits);
}